// round 14
// baseline (speedup 1.0000x reference)
#include <cuda_runtime.h>
#include <math.h>

#define NBOX 98
#define NPAIR 49
#define THREADS 128

__device__ __forceinline__ float sigm(float v) {
    return 1.0f / (1.0f + __expf(-v));
}

__global__ __launch_bounds__(THREADS, 16) void yolo_post_kernel(
    const float* __restrict__ x, float* __restrict__ out, int B)
{
    __shared__ float s_x[1470];
    __shared__ __align__(16) unsigned long long s_pair[NPAIR + 1];  // (score_desc<<32)|(2*cell<<2)|cnt
    __shared__ int s_wcnt[4];

    const int tid = threadIdx.x;
    const int img = blockIdx.x;
    const float* __restrict__ xin = x + (size_t)img * 1470;

    // output base pointers (hoisted)
    float* __restrict__ p_box = out + (size_t)img * (NBOX * 4);
    float* __restrict__ p_sc  = out + (size_t)B * (NBOX * 4) + (size_t)img * NBOX;
    float* __restrict__ p_lb  = p_sc + (size_t)B * NBOX;
    float* __restrict__ p_kp  = p_lb + (size_t)B * NBOX;

    // ---- stage input row (coalesced float2, statically unrolled) ----
    {
        const float2* __restrict__ xin2 = (const float2*)xin;
        float2* __restrict__ sx2 = (float2*)s_x;
        #pragma unroll
        for (int it = 0; it < 6; ++it) {
            const int i = tid + it * THREADS;
            if (i < 735) sx2[i] = xin2[i];
        }
    }
    __syncthreads();

    // ---- decode (convergent; threads >=98 mapped to cell 48, results unused) ----
    const int bt   = (tid < NBOX) ? tid : (96 + (tid & 1));
    const int cell = bt >> 1;
    const int a    = bt & 1;
    const int ci   = cell / 7;
    const int cj   = cell % 7;
    const int abase = cell * 30 + a * 5;

    // half-argmax over 10 classes + pair merge (anchors share class scores)
    float myb = -INFINITY; int mybl = 0;
    {
        const float2* __restrict__ cp = (const float2*)(s_x + cell * 30 + 10) + a * 5;
        const int cb = a * 10;
        #pragma unroll
        for (int c2 = 0; c2 < 5; ++c2) {
            const float2 vv = cp[c2];
            if (vv.x > myb) { myb = vv.x; mybl = cb + 2 * c2; }
            if (vv.y > myb) { myb = vv.y; mybl = cb + 2 * c2 + 1; }
        }
    }
    const float ob  = __shfl_xor_sync(0xFFFFFFFFu, myb, 1);
    const int   obl = __shfl_xor_sync(0xFFFFFFFFu, mybl, 1);
    const float lowb  = a ? ob  : myb;  const int lowl  = a ? obl  : mybl;
    const float highb = a ? myb : ob;   const int highl = a ? mybl : obl;
    const float best = (lowb >= highb) ? lowb : highb;   // first-max == jnp.argmax
    const int   bl   = (lowb >= highb) ? lowl : highl;

    const float to = s_x[abase + 4];
    const bool validf = (tid < NBOX) && (to >= 0.0f);    // sigmoid(to)>=0.5 <=> to>=0

    // coords: cj>=1 forces x1=x2=1 identically (clamp after +64*cj); same for ci in y
    float x1, x2, y1, y2;
    if (cj == 0) {
        const float sx_ = sigm(s_x[abase + 0]);
        x1 = sx_; x2 = fminf(sx_ + sigm(s_x[abase + 2]), 1.0f);
    } else { x1 = 1.0f; x2 = 1.0f; }
    if (ci == 0) {
        const float sy_ = sigm(s_x[abase + 1]);
        y1 = sy_; y2 = fminf(sy_ + sigm(s_x[abase + 3]), 1.0f);
    } else { y1 = 1.0f; y2 = 1.0f; }

    // ---- per-pair key entry (one write per pair, by the even-anchor thread) ----
    const unsigned bal = __ballot_sync(0xFFFFFFFFu, validf);
    const int lane = tid & 31, w = tid >> 5;
    if (lane == 0) s_wcnt[w] = __popc(bal);

    // probe key: score descending, then cell index ascending; cnt bits below
    unsigned long long Kme;
    {
        const unsigned u  = __float_as_uint(best);
        const unsigned ou = (u & 0x80000000u) ? ~u : (u | 0x80000000u);
        Kme = (((unsigned long long)(~ou)) << 32) | (unsigned)((2 * cell) << 2);
    }
    const unsigned vother = (bal >> (lane ^ 1)) & 1u;
    if (tid < NBOX && a == 0) {
        const unsigned cnt = (unsigned)validf + vother;
        s_pair[cell] = Kme | cnt;
    }

    // barrier + valid count (valid boxes occupy sorted prefix [0,V))
    const int V = __syncthreads_count(validf);

    // ---- rank: convergent parity-split scan, LDS.128 (2 entries/load) ----
    // a=0 covers entries 0..23 (+ entry 48), a=1 covers 24..47; union = all 49,
    // each exactly once. rank(pair leader) = sum cnt over strictly-smaller keys;
    // own entry >= Kme so it self-excludes.
    int rk = 0;
    {
        const ulonglong2* __restrict__ sp2 =
            reinterpret_cast<const ulonglong2*>(s_pair);
        const int base2 = a * 12;                 // 16B slots [0,12) or [12,24)
        #pragma unroll
        for (int it = 0; it < 12; ++it) {
            const ulonglong2 e2 = sp2[base2 + it];
            if (e2.x < Kme) rk += (int)(e2.x & 3u);
            if (e2.y < Kme) rk += (int)(e2.y & 3u);
        }
        const unsigned long long e48 = s_pair[48];
        if (a == 0 && e48 < Kme) rk += (int)(e48 & 3u);
    }
    rk += __shfl_xor_sync(0xFFFFFFFFu, rk, 1);           // full pair-leader rank
    const unsigned pv0 = (bal >> (lane & ~1)) & 1u;      // validity of pair's anchor 0
    const int rank = rk + (a ? (int)pv0 : 0);

    // ---- emit exactly once per output position ----
    if (tid < NBOX) {
        bool keep = false;
        int pos;
        if (validf) {
            pos = rank;
            keep = (best >= 0.05f);
            // Structural NMS: every box outside cell(0,0) is clamp-degenerate
            // (zero area) for any input => iou==0; orig0/orig1 share a score so
            // orig0 ranks first and is unsuppressible. Only check: orig1 vs orig0.
            if (keep && bt == 1 && s_x[4] >= 0.0f) {
                const float a0x1 = sigm(s_x[0]);
                const float a0x2 = fminf(a0x1 + sigm(s_x[2]), 1.0f);
                const float a0y1 = sigm(s_x[1]);
                const float a0y2 = fminf(a0y1 + sigm(s_x[3]), 1.0f);
                const float lx = fmaxf(a0x1, x1), ly = fmaxf(a0y1, y1);
                const float rx = fminf(a0x2, x2), ry = fminf(a0y2, y2);
                const float wn = fmaxf(rx - lx, 0.0f), hn = fmaxf(ry - ly, 0.0f);
                const float inter = wn * hn;
                const float uni = (a0x2 - a0x1) * (a0y2 - a0y1)
                                + (x2 - x1) * (y2 - y1) - inter;
                if (uni > 0.0f && inter > 0.7f * uni) keep = false;
            }
        } else {
            // tail slot: V + rank among invalid boxes by original index
            int nvb = __popc(bal & ((1u << lane) - 1u));
            if (w > 0) nvb += s_wcnt[0];
            if (w > 1) nvb += s_wcnt[1];
            if (w > 2) nvb += s_wcnt[2];
            pos = V + (bt - nvb);
        }

        const float4 bb = keep ? make_float4(x1, y1, x2, y2)
                               : make_float4(0.f, 0.f, 0.f, 0.f);
        reinterpret_cast<float4*>(p_box)[pos] = bb;
        p_sc[pos] = keep ? best : 0.f;
        p_lb[pos] = keep ? (float)bl : 0.f;
        p_kp[pos] = keep ? 1.f : 0.f;
    }
}

extern "C" void kernel_launch(void* const* d_in, const int* in_sizes, int n_in,
                              void* d_out, int out_size)
{
    const float* x = (const float*)d_in[0];
    const int B = in_sizes[0] / 1470;
    yolo_post_kernel<<<B, THREADS>>>(x, (float*)d_out, B);
}